// round 15
// baseline (speedup 1.0000x reference)
#include <cuda_runtime.h>
#include <math.h>
#include <stdint.h>

#define MAXB 64
#define MAXP 8732
#define MAXO 16
#define MSPLIT 16                          // P-splits in match kernel
#define TP 256                             // priors per loss block
#define NW (TP / 32)                       // warps per loss block
#define HP 264                             // padded per-warp hist row (ints)
#define ACC_SCALE 67108864.0               // 2^26 fixed-point for deterministic atomics

// ---- scratch (static __device__; no runtime allocation) ----
__device__ unsigned long long g_keypart[MAXB * MAXO * MSPLIT]; // plain stores, no init
__device__ unsigned long long g_pov[MAXB * MAXP];  // per-prior (best_ov_bits<<32)|ti
__device__ float              g_mined[MAXB * MAXP];
__device__ int                g_num_pos[MAXB];
__device__ float              g_negsum[MAXB];
__device__ unsigned long long g_acc_l[MAXB];
__device__ unsigned long long g_acc_c[MAXB];
__device__ int                g_bdone[MAXB];
__device__ unsigned int       g_done;

// ---------------------------------------------------------------------------
// Match: per-truth best prior (min-p tie) AND per-prior best truth (min-o tie).
template <int OO>
__global__ void __launch_bounds__(256)
match_kernel_t(const float* __restrict__ priors,
               const float* __restrict__ targets,
               int P) {
    int b = blockIdx.y;
    int bx = blockIdx.x;
    int tid = threadIdx.x;
    __shared__ float sh_t[OO * 5];
    __shared__ unsigned long long sh_key[OO];

    if (bx == 0 && tid == 0) {
        g_num_pos[b] = 0;
        g_acc_l[b] = 0ull;
        g_acc_c[b] = 0ull;
        g_bdone[b] = 0;
        if (b == 0) g_done = 0u;
    }
    if (tid < OO * 5) sh_t[tid] = targets[b * OO * 5 + tid];
    if (tid < OO)     sh_key[tid] = 0ull;
    __syncthreads();

    float T0[OO], T1[OO], T2[OO], T3[OO], TA[OO];
#pragma unroll
    for (int o = 0; o < OO; o++) {
        T0[o] = sh_t[o * 5 + 0];
        T1[o] = sh_t[o * 5 + 1];
        T2[o] = sh_t[o * 5 + 2];
        T3[o] = sh_t[o * 5 + 3];
        TA[o] = (T2[o] - T0[o]) * (T3[o] - T1[o]);
    }

    int chunk = (P + gridDim.x - 1) / gridDim.x;
    int p0 = bx * chunk;
    int p1 = min(p0 + chunk, P);

    float bv[OO];
    int bp_[OO];
#pragma unroll
    for (int o = 0; o < OO; o++) { bv[o] = -1.f; bp_[o] = 0; }

    const float4* pr4 = (const float4*)priors;
    for (int p = p0 + tid; p < p1; p += blockDim.x) {
        float4 pr = pr4[p];
        float px0 = pr.x - pr.z * 0.5f, py0 = pr.y - pr.w * 0.5f;
        float px1 = pr.x + pr.z * 0.5f, py1 = pr.y + pr.w * 0.5f;
        float areaP = pr.z * pr.w;
        float pb = -1.f; int pti = 0;
#pragma unroll
        for (int o = 0; o < OO; o++) {
            float ltx = fmaxf(T0[o], px0), lty = fmaxf(T1[o], py0);
            float rbx = fminf(T2[o], px1), rby = fminf(T3[o], py1);
            float iw = fmaxf(rbx - ltx, 0.f), ih = fmaxf(rby - lty, 0.f);
            float inter = iw * ih;
            float ov = __fdividef(inter, TA[o] + areaP - inter);
            if (ov > bv[o]) { bv[o] = ov; bp_[o] = p; }   // ascending p -> min-p tie
            if (ov > pb)    { pb = ov; pti = o; }         // ascending o -> min-o tie
        }
        g_pov[(size_t)b * P + p] =
            ((unsigned long long)__float_as_uint(pb) << 32) | (unsigned)pti;
    }

#pragma unroll
    for (int o = 0; o < OO; o++) {
        unsigned long long key = (bv[o] < 0.f) ? 0ull :
            (((unsigned long long)__float_as_uint(bv[o]) << 32) |
             (unsigned long long)(0xFFFFFFFFu - (unsigned)bp_[o]));
#pragma unroll
        for (int off = 16; off; off >>= 1) {
            unsigned long long other = __shfl_down_sync(0xFFFFFFFFu, key, off);
            if (other > key) key = other;
        }
        if ((tid & 31) == 0) atomicMax(&sh_key[o], key);
    }
    __syncthreads();
    if (tid < OO)
        g_keypart[(b * MAXO + tid) * MSPLIT + bx] = sh_key[tid];
}

// Generic fallback (O != 8)
__global__ void __launch_bounds__(256)
match_kernel_gen(const float* __restrict__ priors,
                 const float* __restrict__ targets,
                 int P, int O) {
    int b = blockIdx.y;
    int bx = blockIdx.x;
    int tid = threadIdx.x;
    __shared__ float sh_t[MAXO * 5];
    __shared__ unsigned long long sh_key[MAXO];

    if (bx == 0 && tid == 0) {
        g_num_pos[b] = 0;
        g_acc_l[b] = 0ull;
        g_acc_c[b] = 0ull;
        g_bdone[b] = 0;
        if (b == 0) g_done = 0u;
    }
    if (tid < MAXO) sh_key[tid] = 0ull;
    if (tid < O * 5) sh_t[tid] = targets[b * O * 5 + tid];
    __syncthreads();

    int chunk = (P + gridDim.x - 1) / gridDim.x;
    int p0 = bx * chunk;
    int p1 = min(p0 + chunk, P);

    const float4* pr4 = (const float4*)priors;
    for (int p = p0 + tid; p < p1; p += blockDim.x) {
        float4 pr = pr4[p];
        float px0 = pr.x - pr.z * 0.5f, py0 = pr.y - pr.w * 0.5f;
        float px1 = pr.x + pr.z * 0.5f, py1 = pr.y + pr.w * 0.5f;
        float areaP = pr.z * pr.w;
        float pb = -1.f; int pti = 0;
        for (int o = 0; o < O; o++) {
            float t0 = sh_t[o * 5 + 0], t1 = sh_t[o * 5 + 1];
            float t2 = sh_t[o * 5 + 2], t3 = sh_t[o * 5 + 3];
            float ltx = fmaxf(t0, px0), lty = fmaxf(t1, py0);
            float rbx = fminf(t2, px1), rby = fminf(t3, py1);
            float iw = fmaxf(rbx - ltx, 0.f), ih = fmaxf(rby - lty, 0.f);
            float inter = iw * ih;
            float areaT = (t2 - t0) * (t3 - t1);
            float ov = __fdividef(inter, areaT + areaP - inter);
            if (ov > pb) { pb = ov; pti = o; }
            unsigned long long key =
                ((unsigned long long)__float_as_uint(ov) << 32) |
                (unsigned long long)(0xFFFFFFFFu - (unsigned)p);
            atomicMax(&sh_key[o], key);
        }
        g_pov[(size_t)b * P + p] =
            ((unsigned long long)__float_as_uint(pb) << 32) | (unsigned)pti;
    }
    __syncthreads();
    if (tid < MAXO)
        g_keypart[(b * MAXO + tid) * MSPLIT + bx] = sh_key[tid];
}

// ---------------------------------------------------------------------------
// Fused loss + per-batch mine. Phase 1: thread-per-prior loss. Phase 2 (last
// block of batch b): radix top-k select over g_mined[b] (L2-hot); finalize in
// globally-last block. ALL collective loops use fixed trip counts.
template <int CC, int OO>
__global__ void __launch_bounds__(TP)
loss_mine_kernel(float* __restrict__ out,
                 const float* __restrict__ loc_data,
                 const float* __restrict__ conf_data,
                 const float* __restrict__ priors,
                 const float* __restrict__ targets,
                 int P, int C, int B) {
    int b = blockIdx.y;
    int tid = threadIdx.x;
    int lane = tid & 31;
    int wid = tid >> 5;
    int p0 = blockIdx.x * TP;
    int cnt = min(TP, P - p0);

    __shared__ float sconf[TP * CC];           // >= NW*HP + 256 ints for phase 2
    __shared__ float sh_t[OO * 5];
    __shared__ unsigned sh_win[OO];
    __shared__ float s_rl[NW], s_rc[NW];
    __shared__ int s_rn[NW];
    __shared__ int s_lastb, s_last;
    __shared__ unsigned s_prefix;
    __shared__ int s_kk;
    __shared__ float s_red[NW];

    if (tid < OO * 5) sh_t[tid] = targets[b * OO * 5 + tid];
    if (tid < OO) {
        unsigned long long kmax = 0ull;
        const unsigned long long* kp = g_keypart + (b * MAXO + tid) * MSPLIT;
#pragma unroll
        for (int s = 0; s < MSPLIT; s++) {
            unsigned long long v = kp[s];
            if (v > kmax) kmax = v;
        }
        sh_win[tid] = 0xFFFFFFFFu - (unsigned)(kmax & 0xFFFFFFFFull);
    }

    {
        size_t base = ((size_t)b * P + p0) * C;
        int tot = cnt * C;
        for (int j = tid; j < tot; j += TP)
            sconf[j] = conf_data[base + j];
    }
    __syncthreads();

    float ll = 0.f, cpos = 0.f;
    int np1 = 0;

    if (tid < cnt) {
        int p = p0 + tid;
        size_t bp = (size_t)b * P + p;

        unsigned long long pov = g_pov[bp];
        float bestv = __uint_as_float((unsigned)(pov >> 32));
        int ti = (int)(pov & 0xFFu);
        int ovr = -1;
#pragma unroll
        for (int o = 0; o < OO; o++)
            if (sh_win[o] == (unsigned)p) ovr = o;       // last (highest) o wins
        if (ovr >= 0) { bestv = 2.0f; ti = ovr; }
        int conf_t = (bestv >= 0.5f) ? (int)sh_t[ti * 5 + 4] + 1 : 0;
        bool pos = (conf_t > 0);

        const float* row = sconf + tid * C;
        float m = row[0];
        for (int c = 1; c < C; c++) m = fmaxf(m, row[c]);
        float e = 0.f;
        for (int c = 0; c < C; c++) e += __expf(row[c] - m);
        float lc = m + __logf(e) - row[conf_t];

        g_mined[bp] = pos ? 0.f : lc;
        if (pos) {
            cpos = lc;
            np1 = 1;
            float4 pr = ((const float4*)priors)[p];
            float mx0 = sh_t[ti * 5 + 0], my0 = sh_t[ti * 5 + 1];
            float mx1 = sh_t[ti * 5 + 2], my1 = sh_t[ti * 5 + 3];
            float g0 = ((mx0 + mx1) * 0.5f - pr.x) / (0.1f * pr.z);
            float g1 = ((my0 + my1) * 0.5f - pr.y) / (0.1f * pr.w);
            float g2 = __logf(fmaxf((mx1 - mx0) / pr.z, 1e-8f)) / 0.2f;
            float g3 = __logf(fmaxf((my1 - my0) / pr.w, 1e-8f)) / 0.2f;
            float4 L = ((const float4*)loc_data)[bp];
            float Ld[4] = {L.x, L.y, L.z, L.w};
            float g4[4] = {g0, g1, g2, g3};
#pragma unroll
            for (int i = 0; i < 4; i++) {
                float d = Ld[i] - g4[i];
                float ad = fabsf(d);
                ll += (ad < 1.f) ? 0.5f * d * d : ad - 0.5f;
            }
        }
    }

#pragma unroll
    for (int off = 16; off; off >>= 1) {
        ll   += __shfl_down_sync(0xFFFFFFFFu, ll, off);
        cpos += __shfl_down_sync(0xFFFFFFFFu, cpos, off);
        np1  += __shfl_down_sync(0xFFFFFFFFu, np1, off);
    }
    if (lane == 0) { s_rl[wid] = ll; s_rc[wid] = cpos; s_rn[wid] = np1; }
    __syncthreads();
    if (tid == 0) {
        float tl = 0.f, tc = 0.f; int tn = 0;
#pragma unroll
        for (int w = 0; w < NW; w++) { tl += s_rl[w]; tc += s_rc[w]; tn += s_rn[w]; }
        if (tl != 0.f)
            atomicAdd(&g_acc_l[b], (unsigned long long)(long long)llrint((double)tl * ACC_SCALE));
        if (tc != 0.f)
            atomicAdd(&g_acc_c[b], (unsigned long long)(long long)llrint((double)tc * ACC_SCALE));
        if (tn) atomicAdd(&g_num_pos[b], tn);
        __threadfence();
        int done = atomicAdd(&g_bdone[b], 1);
        s_lastb = (done == (int)gridDim.x - 1) ? 1 : 0;
        if (s_lastb) __threadfence();          // acquire other blocks' writes
    }
    __syncthreads();
    if (!s_lastb) return;

    // ============== phase 2: mine for batch b (last block only) ==============
    int* hist = (int*)sconf;                   // NW*HP ints
    int* merged = hist + NW * HP;              // +256 ints (fits in sconf)

    const float* mv = g_mined + (size_t)b * P;
    int np = g_num_pos[b];
    int k = min(3 * np, P - np);
    float negsum = 0.f;
    int iters = (P + TP - 1) / TP;             // fixed trip count for collectives

    if (k > 0) {
        int* whist = hist + wid * HP;
        unsigned prefix = 0, pmask = 0;
        int kk = k;
        for (int shift = 24; shift >= 0; shift -= 8) {
            for (int idx = tid; idx < NW * HP; idx += TP) hist[idx] = 0;
            __syncthreads();
            for (int it = 0; it < iters; it++) {
                int p = it * TP + tid;
                unsigned key = (p < P) ? __float_as_uint(mv[p]) : 0u;   // L2-hot
                bool valid = (p < P) && ((key & pmask) == prefix);
                unsigned bin = valid ? ((key >> shift) & 0xFFu) : 256u;
                unsigned peers = __match_any_sync(0xFFFFFFFFu, bin);
                if (valid && lane == (__ffs(peers) - 1))
                    atomicAdd(&whist[bin], (int)__popc(peers));
            }
            __syncthreads();
            {
                int m = 0;
#pragma unroll
                for (int w = 0; w < NW; w++) m += hist[w * HP + tid];
                merged[tid] = m;
            }
            __syncthreads();
            if (tid < 32) {
                int base = tid * 8;
                int v[8], suff[8];
#pragma unroll
                for (int i = 0; i < 8; i++) v[i] = merged[base + i];
                int run = 0;
#pragma unroll
                for (int i = 7; i >= 0; i--) { run += v[i]; suff[i] = run; }
                int x = run;
#pragma unroll
                for (int off = 1; off < 32; off <<= 1) {
                    int y = __shfl_down_sync(0xFFFFFFFFu, x, off);
                    if (tid + off < 32) x += y;
                }
                int above = x - run;
#pragma unroll
                for (int i = 0; i < 8; i++) {
                    int ss  = suff[i] + above;
                    int ssn = (i < 7) ? suff[i + 1] + above : above;
                    if (ss >= kk && ssn < kk) {
                        s_prefix = prefix | ((unsigned)(base + i) << shift);
                        s_kk = kk - ssn;
                    }
                }
            }
            __syncthreads();
            prefix = s_prefix;
            kk = s_kk;
            pmask |= 0xFFu << shift;
        }

        float lsum = 0.f;
        for (int it = 0; it < iters; it++) {
            int p = it * TP + tid;
            if (p < P) {
                unsigned key = __float_as_uint(mv[p]);
                if (key > prefix) lsum += __uint_as_float(key);
            }
        }
#pragma unroll
        for (int off = 16; off; off >>= 1)
            lsum += __shfl_xor_sync(0xFFFFFFFFu, lsum, off);
        if (lane == 0) s_red[wid] = lsum;
        __syncthreads();
        if (tid == 0) {
            float tot = 0.f;
#pragma unroll
            for (int i = 0; i < NW; i++) tot += s_red[i];
            negsum = tot + (float)kk * __uint_as_float(prefix);
        }
    }
    if (tid == 0) {
        g_negsum[b] = negsum;
        __threadfence();
        unsigned done = atomicAdd(&g_done, 1u);
        s_last = (done == (unsigned)(B - 1)) ? 1 : 0;
        if (s_last) __threadfence();
    }
    __syncthreads();
    if (s_last && tid < 32) {
        double lld = 0.0, lcd = 0.0;
        int N = 0;
        for (int bb = tid; bb < B; bb += 32) {
            lld += (double)(long long)g_acc_l[bb];
            lcd += (double)(long long)g_acc_c[bb];
            lcd += (double)g_negsum[bb] * ACC_SCALE;
            N += g_num_pos[bb];
        }
#pragma unroll
        for (int off = 16; off; off >>= 1) {
            lld += __shfl_down_sync(0xFFFFFFFFu, lld, off);
            lcd += __shfl_down_sync(0xFFFFFFFFu, lcd, off);
            N   += __shfl_down_sync(0xFFFFFFFFu, N, off);
        }
        if (tid == 0) {
            double fN = (double)N * ACC_SCALE;
            out[0] = (float)(lld / fN);
            out[1] = (float)(lcd / fN);
        }
    }
}

// ---------------------------------------------------------------------------
extern "C" void kernel_launch(void* const* d_in, const int* in_sizes, int n_in,
                              void* d_out, int out_size) {
    const float* loc     = (const float*)d_in[0];
    const float* conf    = (const float*)d_in[1];
    const float* priors  = (const float*)d_in[2];
    const float* targets = (const float*)d_in[3];

    int P = in_sizes[2] / 4;
    int B = in_sizes[0] / (P * 4);
    int C = in_sizes[1] / (B * P);
    int O = in_sizes[3] / (B * 5);
    float* out = (float*)d_out;

    dim3 mgrid(MSPLIT, B);
    if (O == 8)
        match_kernel_t<8><<<mgrid, 256>>>(priors, targets, P);
    else
        match_kernel_gen<<<mgrid, 256>>>(priors, targets, P, O);

    dim3 gridB((P + TP - 1) / TP, B);
    if (O == 8 && C == 21)
        loss_mine_kernel<21, 8><<<gridB, TP>>>(out, loc, conf, priors, targets, P, C, B);
    else if (C <= 32 && O <= 8)
        loss_mine_kernel<32, 8><<<gridB, TP>>>(out, loc, conf, priors, targets, P, C, B);
    else
        loss_mine_kernel<64, MAXO><<<gridB, TP>>>(out, loc, conf, priors, targets, P, C, B);
}

// round 16
// speedup vs baseline: 2.1443x; 2.1443x over previous
#include <cuda_runtime.h>
#include <math.h>
#include <stdint.h>

#define MAXB 64
#define MAXP 8732
#define MAXO 16
#define MSPLIT 16                          // P-splits in match kernel
#define TP 256                             // priors per loss block
#define MB 1024                            // mine block threads
#define NIT ((MAXP + MB - 1) / MB)         // 9 keys per mine thread
#define HP 264                             // padded per-warp hist row (ints)
#define ACC_SCALE 67108864.0               // 2^26 fixed-point for deterministic atomics

// ---- scratch (static __device__; no runtime allocation) ----
__device__ unsigned long long g_keypart[MAXB * MAXO * MSPLIT]; // plain stores, no init
__device__ unsigned long long g_pov[MAXB * MAXP];  // per-prior (best_ov_bits<<32)|ti
__device__ float              g_mined[MAXB * MAXP];
__device__ int                g_num_pos[MAXB];
__device__ float              g_negsum[MAXB];
__device__ unsigned long long g_acc_l[MAXB];
__device__ unsigned long long g_acc_c[MAXB];
__device__ unsigned int       g_done;

// ---------------------------------------------------------------------------
// Match: per-truth best prior (min-p tie) AND per-prior best truth (min-o tie).
template <int OO>
__global__ void __launch_bounds__(256)
match_kernel_t(const float* __restrict__ priors,
               const float* __restrict__ targets,
               int P) {
    int b = blockIdx.y;
    int bx = blockIdx.x;
    int tid = threadIdx.x;
    __shared__ float sh_t[OO * 5];
    __shared__ unsigned long long sh_key[OO];

    if (bx == 0 && tid == 0) {
        g_num_pos[b] = 0;
        g_acc_l[b] = 0ull;
        g_acc_c[b] = 0ull;
        if (b == 0) g_done = 0u;
    }
    if (tid < OO * 5) sh_t[tid] = targets[b * OO * 5 + tid];
    if (tid < OO)     sh_key[tid] = 0ull;
    __syncthreads();

    float T0[OO], T1[OO], T2[OO], T3[OO], TA[OO];
#pragma unroll
    for (int o = 0; o < OO; o++) {
        T0[o] = sh_t[o * 5 + 0];
        T1[o] = sh_t[o * 5 + 1];
        T2[o] = sh_t[o * 5 + 2];
        T3[o] = sh_t[o * 5 + 3];
        TA[o] = (T2[o] - T0[o]) * (T3[o] - T1[o]);
    }

    int chunk = (P + gridDim.x - 1) / gridDim.x;
    int p0 = bx * chunk;
    int p1 = min(p0 + chunk, P);

    float bv[OO];
    int bp_[OO];
#pragma unroll
    for (int o = 0; o < OO; o++) { bv[o] = -1.f; bp_[o] = 0; }

    const float4* pr4 = (const float4*)priors;
    for (int p = p0 + tid; p < p1; p += blockDim.x) {
        float4 pr = pr4[p];
        float px0 = pr.x - pr.z * 0.5f, py0 = pr.y - pr.w * 0.5f;
        float px1 = pr.x + pr.z * 0.5f, py1 = pr.y + pr.w * 0.5f;
        float areaP = pr.z * pr.w;
        float pb = -1.f; int pti = 0;
#pragma unroll
        for (int o = 0; o < OO; o++) {
            float ltx = fmaxf(T0[o], px0), lty = fmaxf(T1[o], py0);
            float rbx = fminf(T2[o], px1), rby = fminf(T3[o], py1);
            float iw = fmaxf(rbx - ltx, 0.f), ih = fmaxf(rby - lty, 0.f);
            float inter = iw * ih;
            float ov = __fdividef(inter, TA[o] + areaP - inter);
            if (ov > bv[o]) { bv[o] = ov; bp_[o] = p; }   // ascending p -> min-p tie
            if (ov > pb)    { pb = ov; pti = o; }         // ascending o -> min-o tie
        }
        g_pov[(size_t)b * P + p] =
            ((unsigned long long)__float_as_uint(pb) << 32) | (unsigned)pti;
    }

#pragma unroll
    for (int o = 0; o < OO; o++) {
        unsigned long long key = (bv[o] < 0.f) ? 0ull :
            (((unsigned long long)__float_as_uint(bv[o]) << 32) |
             (unsigned long long)(0xFFFFFFFFu - (unsigned)bp_[o]));
#pragma unroll
        for (int off = 16; off; off >>= 1) {
            unsigned long long other = __shfl_down_sync(0xFFFFFFFFu, key, off);
            if (other > key) key = other;
        }
        if ((tid & 31) == 0) atomicMax(&sh_key[o], key);
    }
    __syncthreads();
    if (tid < OO)
        g_keypart[(b * MAXO + tid) * MSPLIT + bx] = sh_key[tid];
}

// Generic fallback (O != 8)
__global__ void __launch_bounds__(256)
match_kernel_gen(const float* __restrict__ priors,
                 const float* __restrict__ targets,
                 int P, int O) {
    int b = blockIdx.y;
    int bx = blockIdx.x;
    int tid = threadIdx.x;
    __shared__ float sh_t[MAXO * 5];
    __shared__ unsigned long long sh_key[MAXO];

    if (bx == 0 && tid == 0) {
        g_num_pos[b] = 0;
        g_acc_l[b] = 0ull;
        g_acc_c[b] = 0ull;
        if (b == 0) g_done = 0u;
    }
    if (tid < MAXO) sh_key[tid] = 0ull;
    if (tid < O * 5) sh_t[tid] = targets[b * O * 5 + tid];
    __syncthreads();

    int chunk = (P + gridDim.x - 1) / gridDim.x;
    int p0 = bx * chunk;
    int p1 = min(p0 + chunk, P);

    const float4* pr4 = (const float4*)priors;
    for (int p = p0 + tid; p < p1; p += blockDim.x) {
        float4 pr = pr4[p];
        float px0 = pr.x - pr.z * 0.5f, py0 = pr.y - pr.w * 0.5f;
        float px1 = pr.x + pr.z * 0.5f, py1 = pr.y + pr.w * 0.5f;
        float areaP = pr.z * pr.w;
        float pb = -1.f; int pti = 0;
        for (int o = 0; o < O; o++) {
            float t0 = sh_t[o * 5 + 0], t1 = sh_t[o * 5 + 1];
            float t2 = sh_t[o * 5 + 2], t3 = sh_t[o * 5 + 3];
            float ltx = fmaxf(t0, px0), lty = fmaxf(t1, py0);
            float rbx = fminf(t2, px1), rby = fminf(t3, py1);
            float iw = fmaxf(rbx - ltx, 0.f), ih = fmaxf(rby - lty, 0.f);
            float inter = iw * ih;
            float areaT = (t2 - t0) * (t3 - t1);
            float ov = __fdividef(inter, areaT + areaP - inter);
            if (ov > pb) { pb = ov; pti = o; }
            unsigned long long key =
                ((unsigned long long)__float_as_uint(ov) << 32) |
                (unsigned long long)(0xFFFFFFFFu - (unsigned)p);
            atomicMax(&sh_key[o], key);
        }
        g_pov[(size_t)b * P + p] =
            ((unsigned long long)__float_as_uint(pb) << 32) | (unsigned)pti;
    }
    __syncthreads();
    if (tid < MAXO)
        g_keypart[(b * MAXO + tid) * MSPLIT + bx] = sh_key[tid];
}

// ---------------------------------------------------------------------------
// Thread-per-prior fused loss: conf tile staged in SMEM (float4 when full),
// per-prior match from g_pov, override via reduced g_keypart winners.
// EXACT=true: C == CC at runtime -> compile-time loop bounds.
template <int CC, int OO, bool EXACT>
__global__ void __launch_bounds__(TP)
loss_kernel(const float* __restrict__ loc_data,
            const float* __restrict__ conf_data,
            const float* __restrict__ priors,
            const float* __restrict__ targets,
            int P, int C) {
    int b = blockIdx.y;
    int tid = threadIdx.x;
    int p0 = blockIdx.x * TP;
    int cnt = min(TP, P - p0);
    const int Cn = EXACT ? CC : C;

    __shared__ float sconf[TP * CC];
    __shared__ float sh_t[OO * 5];
    __shared__ unsigned sh_win[OO];
    __shared__ float s_rl[TP / 32], s_rc[TP / 32];
    __shared__ int s_rn[TP / 32];

    if (tid < OO * 5) sh_t[tid] = targets[b * OO * 5 + tid];
    if (tid < OO) {
        unsigned long long kmax = 0ull;
        const unsigned long long* kp = g_keypart + (b * MAXO + tid) * MSPLIT;
#pragma unroll
        for (int s = 0; s < MSPLIT; s++) {
            unsigned long long v = kp[s];
            if (v > kmax) kmax = v;
        }
        sh_win[tid] = 0xFFFFFFFFu - (unsigned)(kmax & 0xFFFFFFFFull);
    }

    {
        size_t base = ((size_t)b * P + p0) * Cn;
        int tot = cnt * Cn;
        if (cnt == TP && ((base & 3) == 0) && ((tot & 3) == 0)) {
            const float4* src = (const float4*)(conf_data + base);
            float4* dst = (float4*)sconf;
            int tot4 = tot >> 2;
            for (int j = tid; j < tot4; j += TP)
                dst[j] = src[j];
        } else {
            for (int j = tid; j < tot; j += TP)
                sconf[j] = conf_data[base + j];
        }
    }
    __syncthreads();

    float ll = 0.f, cpos = 0.f;
    int np = 0;

    if (tid < cnt) {
        int p = p0 + tid;
        size_t bp = (size_t)b * P + p;

        unsigned long long pov = g_pov[bp];
        float bestv = __uint_as_float((unsigned)(pov >> 32));
        int ti = (int)(pov & 0xFFu);
        int ovr = -1;
#pragma unroll
        for (int o = 0; o < OO; o++)
            if (sh_win[o] == (unsigned)p) ovr = o;       // last (highest) o wins
        if (ovr >= 0) { bestv = 2.0f; ti = ovr; }
        int conf_t = (bestv >= 0.5f) ? (int)sh_t[ti * 5 + 4] + 1 : 0;
        bool pos = (conf_t > 0);

        const float* row = sconf + tid * Cn;
        float m = row[0];
#pragma unroll
        for (int c = 1; c < (EXACT ? CC : 1024); c++) {
            if (!EXACT && c >= Cn) break;
            m = fmaxf(m, row[c]);
        }
        float e = 0.f;
#pragma unroll
        for (int c = 0; c < (EXACT ? CC : 1024); c++) {
            if (!EXACT && c >= Cn) break;
            e += __expf(row[c] - m);
        }
        float lc = m + __logf(e) - row[conf_t];

        g_mined[bp] = pos ? 0.f : lc;
        if (pos) {
            cpos = lc;
            np = 1;
            float4 pr = ((const float4*)priors)[p];
            float mx0 = sh_t[ti * 5 + 0], my0 = sh_t[ti * 5 + 1];
            float mx1 = sh_t[ti * 5 + 2], my1 = sh_t[ti * 5 + 3];
            float g0 = ((mx0 + mx1) * 0.5f - pr.x) / (0.1f * pr.z);
            float g1 = ((my0 + my1) * 0.5f - pr.y) / (0.1f * pr.w);
            float g2 = __logf(fmaxf((mx1 - mx0) / pr.z, 1e-8f)) / 0.2f;
            float g3 = __logf(fmaxf((my1 - my0) / pr.w, 1e-8f)) / 0.2f;
            float4 L = ((const float4*)loc_data)[bp];
            float Ld[4] = {L.x, L.y, L.z, L.w};
            float g4[4] = {g0, g1, g2, g3};
#pragma unroll
            for (int i = 0; i < 4; i++) {
                float d = Ld[i] - g4[i];
                float ad = fabsf(d);
                ll += (ad < 1.f) ? 0.5f * d * d : ad - 0.5f;
            }
        }
    }

    int lane = tid & 31;
#pragma unroll
    for (int off = 16; off; off >>= 1) {
        ll   += __shfl_down_sync(0xFFFFFFFFu, ll, off);
        cpos += __shfl_down_sync(0xFFFFFFFFu, cpos, off);
        np   += __shfl_down_sync(0xFFFFFFFFu, np, off);
    }
    if (lane == 0) { s_rl[tid >> 5] = ll; s_rc[tid >> 5] = cpos; s_rn[tid >> 5] = np; }
    __syncthreads();
    if (tid == 0) {
        float tl = 0.f, tc = 0.f; int tn = 0;
#pragma unroll
        for (int w = 0; w < TP / 32; w++) { tl += s_rl[w]; tc += s_rc[w]; tn += s_rn[w]; }
        if (tl != 0.f)
            atomicAdd(&g_acc_l[b], (unsigned long long)(long long)llrint((double)tl * ACC_SCALE));
        if (tc != 0.f)
            atomicAdd(&g_acc_c[b], (unsigned long long)(long long)llrint((double)tc * ACC_SCALE));
        if (tn) atomicAdd(&g_num_pos[b], tn);
    }
}

// ---------------------------------------------------------------------------
// Per-batch radix-select of top-k mined conf losses. Keys in registers,
// per-warp privatized histograms, warp-0 register suffix-scan.
__global__ void __launch_bounds__(MB, 1)
mine_kernel(float* __restrict__ out, int P, int B) {
    int b = blockIdx.x;
    int tid = threadIdx.x;
    int lane = tid & 31;
    int wid = tid >> 5;

    __shared__ int hist[32 * HP];      // per-warp rows (padded), ~33.8 KB
    __shared__ int merged[256];
    __shared__ unsigned s_prefix;
    __shared__ int s_kk;
    __shared__ float s_red[MB / 32];
    __shared__ int s_last;

    unsigned key[NIT];
    bool own[NIT];
    const float* mv = g_mined + (size_t)b * P;
#pragma unroll
    for (int i = 0; i < NIT; i++) {
        int p = i * MB + tid;
        own[i] = (p < P);
        key[i] = own[i] ? __float_as_uint(mv[p]) : 0u;
    }

    int np = g_num_pos[b];
    int k = min(3 * np, P - np);
    float negsum = 0.f;

    if (k > 0) {
        int* whist = hist + wid * HP;
        unsigned prefix = 0, pmask = 0;
        int kk = k;
        for (int shift = 24; shift >= 0; shift -= 8) {
#pragma unroll
            for (int j = 0; j < (32 * HP + MB - 1) / MB; j++) {
                int idx = j * MB + tid;
                if (idx < 32 * HP) hist[idx] = 0;
            }
            __syncthreads();
#pragma unroll
            for (int i = 0; i < NIT; i++) {
                bool valid = own[i] && ((key[i] & pmask) == prefix);
                unsigned bin = valid ? ((key[i] >> shift) & 0xFFu) : 256u;
                unsigned peers = __match_any_sync(0xFFFFFFFFu, bin);
                if (valid && lane == (__ffs(peers) - 1))
                    atomicAdd(&whist[bin], (int)__popc(peers));
            }
            __syncthreads();
            if (tid < 256) {
                int m = 0;
#pragma unroll
                for (int w = 0; w < 32; w++) m += hist[w * HP + tid];
                merged[tid] = m;
            }
            __syncthreads();
            if (tid < 32) {
                int base = tid * 8;
                int v[8], suff[8];
#pragma unroll
                for (int i = 0; i < 8; i++) v[i] = merged[base + i];
                int run = 0;
#pragma unroll
                for (int i = 7; i >= 0; i--) { run += v[i]; suff[i] = run; }
                int x = run;
#pragma unroll
                for (int off = 1; off < 32; off <<= 1) {
                    int y = __shfl_down_sync(0xFFFFFFFFu, x, off);
                    if (tid + off < 32) x += y;
                }
                int above = x - run;      // sum over lanes > tid
#pragma unroll
                for (int i = 0; i < 8; i++) {
                    int ss  = suff[i] + above;
                    int ssn = (i < 7) ? suff[i + 1] + above : above;
                    if (ss >= kk && ssn < kk) {
                        s_prefix = prefix | ((unsigned)(base + i) << shift);
                        s_kk = kk - ssn;
                    }
                }
            }
            __syncthreads();
            prefix = s_prefix;
            kk = s_kk;
            pmask |= 0xFFu << shift;
        }

        float lsum = 0.f;
#pragma unroll
        for (int i = 0; i < NIT; i++)
            if (own[i] && key[i] > prefix) lsum += __uint_as_float(key[i]);
#pragma unroll
        for (int off = 16; off; off >>= 1)
            lsum += __shfl_xor_sync(0xFFFFFFFFu, lsum, off);
        if (lane == 0) s_red[wid] = lsum;
        __syncthreads();
        if (tid == 0) {
            float tot = 0.f;
#pragma unroll
            for (int i = 0; i < MB / 32; i++) tot += s_red[i];
            negsum = tot + (float)kk * __uint_as_float(prefix);
        }
    }
    if (tid == 0) {
        g_negsum[b] = negsum;
        __threadfence();
        unsigned done = atomicAdd(&g_done, 1u);
        s_last = (done == (unsigned)(B - 1)) ? 1 : 0;
        if (s_last) __threadfence();
    }
    __syncthreads();
    if (s_last && tid < 32) {
        double ll = 0.0, lc = 0.0;
        int N = 0;
        for (int bb = tid; bb < B; bb += 32) {
            ll += (double)(long long)g_acc_l[bb];
            lc += (double)(long long)g_acc_c[bb];
            lc += (double)g_negsum[bb] * ACC_SCALE;
            N += g_num_pos[bb];
        }
#pragma unroll
        for (int off = 16; off; off >>= 1) {
            ll += __shfl_down_sync(0xFFFFFFFFu, ll, off);
            lc += __shfl_down_sync(0xFFFFFFFFu, lc, off);
            N  += __shfl_down_sync(0xFFFFFFFFu, N, off);
        }
        if (tid == 0) {
            double fN = (double)N * ACC_SCALE;
            out[0] = (float)(ll / fN);
            out[1] = (float)(lc / fN);
        }
    }
}

// ---------------------------------------------------------------------------
extern "C" void kernel_launch(void* const* d_in, const int* in_sizes, int n_in,
                              void* d_out, int out_size) {
    const float* loc     = (const float*)d_in[0];
    const float* conf    = (const float*)d_in[1];
    const float* priors  = (const float*)d_in[2];
    const float* targets = (const float*)d_in[3];

    int P = in_sizes[2] / 4;
    int B = in_sizes[0] / (P * 4);
    int C = in_sizes[1] / (B * P);
    int O = in_sizes[3] / (B * 5);
    float* out = (float*)d_out;

    dim3 mgrid(MSPLIT, B);
    if (O == 8)
        match_kernel_t<8><<<mgrid, 256>>>(priors, targets, P);
    else
        match_kernel_gen<<<mgrid, 256>>>(priors, targets, P, O);

    dim3 gridB((P + TP - 1) / TP, B);
    if (O == 8 && C == 21)
        loss_kernel<21, 8, true><<<gridB, TP>>>(loc, conf, priors, targets, P, C);
    else if (C <= 32 && O <= 8)
        loss_kernel<32, 8, false><<<gridB, TP>>>(loc, conf, priors, targets, P, C);
    else
        loss_kernel<64, MAXO, false><<<gridB, TP>>>(loc, conf, priors, targets, P, C);

    mine_kernel<<<B, MB>>>(out, P, B);
}

// round 17
// speedup vs baseline: 2.2466x; 1.0477x over previous
#include <cuda_runtime.h>
#include <math.h>
#include <stdint.h>

#define MAXB 64
#define MAXP 8732
#define MAXO 16
#define MSPLIT 16                          // P-splits in match kernel
#define TP 256                             // priors per loss block
#define MB 1024                            // mine block threads
#define NIT ((MAXP + MB - 1) / MB)         // 9 keys per mine thread
#define NR 16                              // privatized hist rows in mine
#define HP 264                             // padded hist row (ints)
#define ACC_SCALE 67108864.0               // 2^26 fixed-point for deterministic atomics

// ---- scratch (static __device__; no runtime allocation) ----
__device__ unsigned long long g_keypart[MAXB * MAXO * MSPLIT]; // plain stores, no init
__device__ unsigned long long g_pov[MAXB * MAXP];  // per-prior (best_ov_bits<<32)|ti
__device__ float              g_mined[MAXB * MAXP];
__device__ int                g_num_pos[MAXB];
__device__ float              g_negsum[MAXB];
__device__ unsigned long long g_acc_l[MAXB];
__device__ unsigned long long g_acc_c[MAXB];
__device__ unsigned int       g_done;

// ---------------------------------------------------------------------------
// Match: per-truth best prior (min-p tie) AND per-prior best truth (min-o tie).
template <int OO>
__global__ void __launch_bounds__(256, 4)
match_kernel_t(const float* __restrict__ priors,
               const float* __restrict__ targets,
               int P) {
    int b = blockIdx.y;
    int bx = blockIdx.x;
    int tid = threadIdx.x;
    __shared__ float sh_t[OO * 5];
    __shared__ unsigned long long sh_key[OO];

    if (bx == 0 && tid == 0) {
        g_num_pos[b] = 0;
        g_acc_l[b] = 0ull;
        g_acc_c[b] = 0ull;
        if (b == 0) g_done = 0u;
    }
    if (tid < OO * 5) sh_t[tid] = targets[b * OO * 5 + tid];
    if (tid < OO)     sh_key[tid] = 0ull;
    __syncthreads();

    float T0[OO], T1[OO], T2[OO], T3[OO], TA[OO];
#pragma unroll
    for (int o = 0; o < OO; o++) {
        T0[o] = sh_t[o * 5 + 0];
        T1[o] = sh_t[o * 5 + 1];
        T2[o] = sh_t[o * 5 + 2];
        T3[o] = sh_t[o * 5 + 3];
        TA[o] = (T2[o] - T0[o]) * (T3[o] - T1[o]);
    }

    int chunk = (P + gridDim.x - 1) / gridDim.x;
    int p0 = bx * chunk;
    int p1 = min(p0 + chunk, P);

    float bv[OO];
    int bp_[OO];
#pragma unroll
    for (int o = 0; o < OO; o++) { bv[o] = -1.f; bp_[o] = 0; }

    const float4* pr4 = (const float4*)priors;
    for (int p = p0 + tid; p < p1; p += blockDim.x) {
        float4 pr = pr4[p];
        float px0 = pr.x - pr.z * 0.5f, py0 = pr.y - pr.w * 0.5f;
        float px1 = pr.x + pr.z * 0.5f, py1 = pr.y + pr.w * 0.5f;
        float areaP = pr.z * pr.w;
        float pb = -1.f; int pti = 0;
#pragma unroll
        for (int o = 0; o < OO; o++) {
            float ltx = fmaxf(T0[o], px0), lty = fmaxf(T1[o], py0);
            float rbx = fminf(T2[o], px1), rby = fminf(T3[o], py1);
            float iw = fmaxf(rbx - ltx, 0.f), ih = fmaxf(rby - lty, 0.f);
            float inter = iw * ih;
            float ov = __fdividef(inter, TA[o] + areaP - inter);
            if (ov > bv[o]) { bv[o] = ov; bp_[o] = p; }   // ascending p -> min-p tie
            if (ov > pb)    { pb = ov; pti = o; }         // ascending o -> min-o tie
        }
        g_pov[(size_t)b * P + p] =
            ((unsigned long long)__float_as_uint(pb) << 32) | (unsigned)pti;
    }

#pragma unroll
    for (int o = 0; o < OO; o++) {
        unsigned long long key = (bv[o] < 0.f) ? 0ull :
            (((unsigned long long)__float_as_uint(bv[o]) << 32) |
             (unsigned long long)(0xFFFFFFFFu - (unsigned)bp_[o]));
#pragma unroll
        for (int off = 16; off; off >>= 1) {
            unsigned long long other = __shfl_down_sync(0xFFFFFFFFu, key, off);
            if (other > key) key = other;
        }
        if ((tid & 31) == 0) atomicMax(&sh_key[o], key);
    }
    __syncthreads();
    if (tid < OO)
        g_keypart[(b * MAXO + tid) * MSPLIT + bx] = sh_key[tid];
}

// Generic fallback (O != 8)
__global__ void __launch_bounds__(256)
match_kernel_gen(const float* __restrict__ priors,
                 const float* __restrict__ targets,
                 int P, int O) {
    int b = blockIdx.y;
    int bx = blockIdx.x;
    int tid = threadIdx.x;
    __shared__ float sh_t[MAXO * 5];
    __shared__ unsigned long long sh_key[MAXO];

    if (bx == 0 && tid == 0) {
        g_num_pos[b] = 0;
        g_acc_l[b] = 0ull;
        g_acc_c[b] = 0ull;
        if (b == 0) g_done = 0u;
    }
    if (tid < MAXO) sh_key[tid] = 0ull;
    if (tid < O * 5) sh_t[tid] = targets[b * O * 5 + tid];
    __syncthreads();

    int chunk = (P + gridDim.x - 1) / gridDim.x;
    int p0 = bx * chunk;
    int p1 = min(p0 + chunk, P);

    const float4* pr4 = (const float4*)priors;
    for (int p = p0 + tid; p < p1; p += blockDim.x) {
        float4 pr = pr4[p];
        float px0 = pr.x - pr.z * 0.5f, py0 = pr.y - pr.w * 0.5f;
        float px1 = pr.x + pr.z * 0.5f, py1 = pr.y + pr.w * 0.5f;
        float areaP = pr.z * pr.w;
        float pb = -1.f; int pti = 0;
        for (int o = 0; o < O; o++) {
            float t0 = sh_t[o * 5 + 0], t1 = sh_t[o * 5 + 1];
            float t2 = sh_t[o * 5 + 2], t3 = sh_t[o * 5 + 3];
            float ltx = fmaxf(t0, px0), lty = fmaxf(t1, py0);
            float rbx = fminf(t2, px1), rby = fminf(t3, py1);
            float iw = fmaxf(rbx - ltx, 0.f), ih = fmaxf(rby - lty, 0.f);
            float inter = iw * ih;
            float areaT = (t2 - t0) * (t3 - t1);
            float ov = __fdividef(inter, areaT + areaP - inter);
            if (ov > pb) { pb = ov; pti = o; }
            unsigned long long key =
                ((unsigned long long)__float_as_uint(ov) << 32) |
                (unsigned long long)(0xFFFFFFFFu - (unsigned)p);
            atomicMax(&sh_key[o], key);
        }
        g_pov[(size_t)b * P + p] =
            ((unsigned long long)__float_as_uint(pb) << 32) | (unsigned)pti;
    }
    __syncthreads();
    if (tid < MAXO)
        g_keypart[(b * MAXO + tid) * MSPLIT + bx] = sh_key[tid];
}

// ---------------------------------------------------------------------------
// Thread-per-prior fused loss: pov/priors loads hoisted above the staging
// barrier; conf tile staged in SMEM (float4 when aligned); override via
// reduced g_keypart winners. EXACT: compile-time class-loop bounds.
template <int CC, int OO, bool EXACT>
__global__ void __launch_bounds__(TP)
loss_kernel(const float* __restrict__ loc_data,
            const float* __restrict__ conf_data,
            const float* __restrict__ priors,
            const float* __restrict__ targets,
            int P, int C) {
    int b = blockIdx.y;
    int tid = threadIdx.x;
    int p0 = blockIdx.x * TP;
    int cnt = min(TP, P - p0);
    const int Cn = EXACT ? CC : C;

    __shared__ float sconf[TP * CC];
    __shared__ float sh_t[OO * 5];
    __shared__ unsigned sh_win[OO];
    __shared__ float s_rl[TP / 32], s_rc[TP / 32];
    __shared__ int s_rn[TP / 32];

    if (tid < OO * 5) sh_t[tid] = targets[b * OO * 5 + tid];
    if (tid < OO) {
        unsigned long long kmax = 0ull;
        const unsigned long long* kp = g_keypart + (b * MAXO + tid) * MSPLIT;
#pragma unroll
        for (int s = 0; s < MSPLIT; s++) {
            unsigned long long v = kp[s];
            if (v > kmax) kmax = v;
        }
        sh_win[tid] = 0xFFFFFFFFu - (unsigned)(kmax & 0xFFFFFFFFull);
    }

    // hoisted per-thread loads (independent of sconf)
    int p = p0 + tid;
    size_t bp = (size_t)b * P + p;
    unsigned long long pov = 0ull;
    float4 pr = make_float4(1.f, 1.f, 1.f, 1.f);
    float4 L = make_float4(0.f, 0.f, 0.f, 0.f);
    if (tid < cnt) {
        pov = g_pov[bp];
        pr = ((const float4*)priors)[p];
        L = ((const float4*)loc_data)[bp];
    }

    {
        size_t base = ((size_t)b * P + p0) * Cn;
        int tot = cnt * Cn;
        if (cnt == TP && ((base & 3) == 0) && ((tot & 3) == 0)) {
            const float4* src = (const float4*)(conf_data + base);
            float4* dst = (float4*)sconf;
            int tot4 = tot >> 2;
            for (int j = tid; j < tot4; j += TP)
                dst[j] = src[j];
        } else {
            for (int j = tid; j < tot; j += TP)
                sconf[j] = conf_data[base + j];
        }
    }
    __syncthreads();

    float ll = 0.f, cpos = 0.f;
    int np = 0;

    if (tid < cnt) {
        float bestv = __uint_as_float((unsigned)(pov >> 32));
        int ti = (int)(pov & 0xFFu);
        int ovr = -1;
#pragma unroll
        for (int o = 0; o < OO; o++)
            if (sh_win[o] == (unsigned)p) ovr = o;       // last (highest) o wins
        if (ovr >= 0) { bestv = 2.0f; ti = ovr; }
        int conf_t = (bestv >= 0.5f) ? (int)sh_t[ti * 5 + 4] + 1 : 0;
        bool pos = (conf_t > 0);

        const float* row = sconf + tid * Cn;
        float m = row[0];
#pragma unroll
        for (int c = 1; c < (EXACT ? CC : 1024); c++) {
            if (!EXACT && c >= Cn) break;
            m = fmaxf(m, row[c]);
        }
        float e = 0.f;
#pragma unroll
        for (int c = 0; c < (EXACT ? CC : 1024); c++) {
            if (!EXACT && c >= Cn) break;
            e += __expf(row[c] - m);
        }
        float lc = m + __logf(e) - row[conf_t];

        g_mined[bp] = pos ? 0.f : lc;
        if (pos) {
            cpos = lc;
            np = 1;
            float mx0 = sh_t[ti * 5 + 0], my0 = sh_t[ti * 5 + 1];
            float mx1 = sh_t[ti * 5 + 2], my1 = sh_t[ti * 5 + 3];
            float g0 = ((mx0 + mx1) * 0.5f - pr.x) / (0.1f * pr.z);
            float g1 = ((my0 + my1) * 0.5f - pr.y) / (0.1f * pr.w);
            float g2 = __logf(fmaxf((mx1 - mx0) / pr.z, 1e-8f)) / 0.2f;
            float g3 = __logf(fmaxf((my1 - my0) / pr.w, 1e-8f)) / 0.2f;
            float Ld[4] = {L.x, L.y, L.z, L.w};
            float g4[4] = {g0, g1, g2, g3};
#pragma unroll
            for (int i = 0; i < 4; i++) {
                float d = Ld[i] - g4[i];
                float ad = fabsf(d);
                ll += (ad < 1.f) ? 0.5f * d * d : ad - 0.5f;
            }
        }
    }

    int lane = tid & 31;
#pragma unroll
    for (int off = 16; off; off >>= 1) {
        ll   += __shfl_down_sync(0xFFFFFFFFu, ll, off);
        cpos += __shfl_down_sync(0xFFFFFFFFu, cpos, off);
        np   += __shfl_down_sync(0xFFFFFFFFu, np, off);
    }
    if (lane == 0) { s_rl[tid >> 5] = ll; s_rc[tid >> 5] = cpos; s_rn[tid >> 5] = np; }
    __syncthreads();
    if (tid == 0) {
        float tl = 0.f, tc = 0.f; int tn = 0;
#pragma unroll
        for (int w = 0; w < TP / 32; w++) { tl += s_rl[w]; tc += s_rc[w]; tn += s_rn[w]; }
        if (tl != 0.f)
            atomicAdd(&g_acc_l[b], (unsigned long long)(long long)llrint((double)tl * ACC_SCALE));
        if (tc != 0.f)
            atomicAdd(&g_acc_c[b], (unsigned long long)(long long)llrint((double)tc * ACC_SCALE));
        if (tn) atomicAdd(&g_num_pos[b], tn);
    }
}

// ---------------------------------------------------------------------------
// Per-batch radix-select of top-k mined conf losses. Keys in registers,
// NR privatized hist rows (2 warps/row), warp-0 register suffix-scan.
__global__ void __launch_bounds__(MB, 1)
mine_kernel(float* __restrict__ out, int P, int B) {
    int b = blockIdx.x;
    int tid = threadIdx.x;
    int lane = tid & 31;
    int wid = tid >> 5;

    __shared__ int hist[NR * HP];      // privatized rows, ~16.9 KB
    __shared__ int merged[256];
    __shared__ unsigned s_prefix;
    __shared__ int s_kk;
    __shared__ float s_red[MB / 32];
    __shared__ int s_last;

    unsigned key[NIT];
    bool own[NIT];
    const float* mv = g_mined + (size_t)b * P;
#pragma unroll
    for (int i = 0; i < NIT; i++) {
        int p = i * MB + tid;
        own[i] = (p < P);
        key[i] = own[i] ? __float_as_uint(mv[p]) : 0u;
    }

    int np = g_num_pos[b];
    int k = min(3 * np, P - np);
    float negsum = 0.f;

    if (k > 0) {
        int* whist = hist + (wid & (NR - 1)) * HP;
        unsigned prefix = 0, pmask = 0;
        int kk = k;
        for (int shift = 24; shift >= 0; shift -= 8) {
#pragma unroll
            for (int j = 0; j < (NR * HP + MB - 1) / MB; j++) {
                int idx = j * MB + tid;
                if (idx < NR * HP) hist[idx] = 0;
            }
            __syncthreads();
#pragma unroll
            for (int i = 0; i < NIT; i++) {
                bool valid = own[i] && ((key[i] & pmask) == prefix);
                unsigned bin = valid ? ((key[i] >> shift) & 0xFFu) : 256u;
                unsigned peers = __match_any_sync(0xFFFFFFFFu, bin);
                if (valid && lane == (__ffs(peers) - 1))
                    atomicAdd(&whist[bin], (int)__popc(peers));
            }
            __syncthreads();
            if (tid < 256) {
                int m = 0;
#pragma unroll
                for (int w = 0; w < NR; w++) m += hist[w * HP + tid];
                merged[tid] = m;
            }
            __syncthreads();
            if (tid < 32) {
                int base = tid * 8;
                int v[8], suff[8];
#pragma unroll
                for (int i = 0; i < 8; i++) v[i] = merged[base + i];
                int run = 0;
#pragma unroll
                for (int i = 7; i >= 0; i--) { run += v[i]; suff[i] = run; }
                int x = run;
#pragma unroll
                for (int off = 1; off < 32; off <<= 1) {
                    int y = __shfl_down_sync(0xFFFFFFFFu, x, off);
                    if (tid + off < 32) x += y;
                }
                int above = x - run;      // sum over lanes > tid
#pragma unroll
                for (int i = 0; i < 8; i++) {
                    int ss  = suff[i] + above;
                    int ssn = (i < 7) ? suff[i + 1] + above : above;
                    if (ss >= kk && ssn < kk) {
                        s_prefix = prefix | ((unsigned)(base + i) << shift);
                        s_kk = kk - ssn;
                    }
                }
            }
            __syncthreads();
            prefix = s_prefix;
            kk = s_kk;
            pmask |= 0xFFu << shift;
        }

        float lsum = 0.f;
#pragma unroll
        for (int i = 0; i < NIT; i++)
            if (own[i] && key[i] > prefix) lsum += __uint_as_float(key[i]);
#pragma unroll
        for (int off = 16; off; off >>= 1)
            lsum += __shfl_xor_sync(0xFFFFFFFFu, lsum, off);
        if (lane == 0) s_red[wid] = lsum;
        __syncthreads();
        if (tid == 0) {
            float tot = 0.f;
#pragma unroll
            for (int i = 0; i < MB / 32; i++) tot += s_red[i];
            negsum = tot + (float)kk * __uint_as_float(prefix);
        }
    }
    if (tid == 0) {
        g_negsum[b] = negsum;
        __threadfence();
        unsigned done = atomicAdd(&g_done, 1u);
        s_last = (done == (unsigned)(B - 1)) ? 1 : 0;
        if (s_last) __threadfence();
    }
    __syncthreads();
    if (s_last && tid < 32) {
        double ll = 0.0, lc = 0.0;
        int N = 0;
        for (int bb = tid; bb < B; bb += 32) {
            ll += (double)(long long)g_acc_l[bb];
            lc += (double)(long long)g_acc_c[bb];
            lc += (double)g_negsum[bb] * ACC_SCALE;
            N += g_num_pos[bb];
        }
#pragma unroll
        for (int off = 16; off; off >>= 1) {
            ll += __shfl_down_sync(0xFFFFFFFFu, ll, off);
            lc += __shfl_down_sync(0xFFFFFFFFu, lc, off);
            N  += __shfl_down_sync(0xFFFFFFFFu, N, off);
        }
        if (tid == 0) {
            double fN = (double)N * ACC_SCALE;
            out[0] = (float)(ll / fN);
            out[1] = (float)(lc / fN);
        }
    }
}

// ---------------------------------------------------------------------------
extern "C" void kernel_launch(void* const* d_in, const int* in_sizes, int n_in,
                              void* d_out, int out_size) {
    const float* loc     = (const float*)d_in[0];
    const float* conf    = (const float*)d_in[1];
    const float* priors  = (const float*)d_in[2];
    const float* targets = (const float*)d_in[3];

    int P = in_sizes[2] / 4;
    int B = in_sizes[0] / (P * 4);
    int C = in_sizes[1] / (B * P);
    int O = in_sizes[3] / (B * 5);
    float* out = (float*)d_out;

    dim3 mgrid(MSPLIT, B);
    if (O == 8)
        match_kernel_t<8><<<mgrid, 256>>>(priors, targets, P);
    else
        match_kernel_gen<<<mgrid, 256>>>(priors, targets, P, O);

    dim3 gridB((P + TP - 1) / TP, B);
    if (O == 8 && C == 21)
        loss_kernel<21, 8, true><<<gridB, TP>>>(loc, conf, priors, targets, P, C);
    else if (C <= 32 && O <= 8)
        loss_kernel<32, 8, false><<<gridB, TP>>>(loc, conf, priors, targets, P, C);
    else
        loss_kernel<64, MAXO, false><<<gridB, TP>>>(loc, conf, priors, targets, P, C);

    mine_kernel<<<B, MB>>>(out, P, B);
}